// round 2
// baseline (speedup 1.0000x reference)
#include <cuda_runtime.h>
#include <cuda_bf16.h>
#include <cstdint>

// FeatureBank: new_memory = memory; rows y get w / ||w||, w = 0.5*memory[y] + 0.5*x
//
// Inputs (metadata order): x [4096,128] f32, y [4096] int32, memory [500000,128] f32
// Output: new_memory [500000,128] f32

#define MOMENTUM 0.5f
#define DIM 128
#define BATCH 4096

// One warp per row. Lane l handles float4 at dim offset l*4.
__global__ void featurebank_update_kernel(const float* __restrict__ x,
                                          const int* __restrict__ y,
                                          const float* __restrict__ memory,
                                          float* __restrict__ out) {
    int warp_id = (blockIdx.x * blockDim.x + threadIdx.x) >> 5;
    int lane = threadIdx.x & 31;
    if (warp_id >= BATCH) return;

    int row = y[warp_id];

    const float4* xr = reinterpret_cast<const float4*>(x + (size_t)warp_id * DIM);
    const float4* mr = reinterpret_cast<const float4*>(memory + (size_t)row * DIM);

    float4 xv = xr[lane];
    float4 mv = mr[lane];

    float4 w;
    w.x = mv.x * MOMENTUM + xv.x * (1.0f - MOMENTUM);
    w.y = mv.y * MOMENTUM + xv.y * (1.0f - MOMENTUM);
    w.z = mv.z * MOMENTUM + xv.z * (1.0f - MOMENTUM);
    w.w = mv.w * MOMENTUM + xv.w * (1.0f - MOMENTUM);

    float ss = w.x * w.x + w.y * w.y + w.z * w.z + w.w * w.w;
    // warp reduction over 32 lanes
    #pragma unroll
    for (int off = 16; off > 0; off >>= 1)
        ss += __shfl_xor_sync(0xFFFFFFFFu, ss, off);

    float inv = rsqrtf(ss);

    float4 o;
    o.x = w.x * inv;
    o.y = w.y * inv;
    o.z = w.z * inv;
    o.w = w.w * inv;

    float4* orow = reinterpret_cast<float4*>(out + (size_t)row * DIM);
    orow[lane] = o;
}

extern "C" void kernel_launch(void* const* d_in, const int* in_sizes, int n_in,
                              void* d_out, int out_size) {
    const float* x      = (const float*)d_in[0];
    const int*   y      = (const int*)d_in[1];
    const float* memory = (const float*)d_in[2];
    float*       out    = (float*)d_out;

    size_t bank_bytes = (size_t)out_size * sizeof(float);  // 500000*128*4 = 256 MB

    // Bulk copy of the bank (dominant cost, HBM-bound)
    cudaMemcpyAsync(out, memory, bank_bytes, cudaMemcpyDeviceToDevice);

    // Overwrite the 4096 updated rows (same stream -> ordered after the copy)
    const int threads = 256;                 // 8 warps/block
    const int blocks = (BATCH * 32 + threads - 1) / threads;  // 512 blocks
    featurebank_update_kernel<<<blocks, threads>>>(x, y, memory, out);
}